// round 15
// baseline (speedup 1.0000x reference)
#include <cuda_runtime.h>
#include <cuda_bf16.h>
#include <math.h>

// TorchGemma4VisionPooler: 2x2 average pool over a dense 64x64 patch grid,
// scaled by sqrt(H). B=8, S=4096, H=1152, OUT_LEN=1024.
//
// R14 resubmit (six prior attempts hit infra GPU-acquisition timeouts).
// = R5, best measured: 28.5us total, 27.0us kernel, 76.8% DRAM.
// R6/R8's exact-factorization variant regressed (28.35us kernel, 73.3% DRAM):
// its grid stride (294912 = 1024*288) is an exact multiple of the row width,
// so every thread revisits the same address phase each iteration (fixed
// 37.7MB delta), which can resonate with the L2 set/die hash. R5's stride
// (303104) rotates phase across iterations.
//
// Persistent grid-stride kernel — one resident wave (148 SMs x 8 CTAs x
// 256 thr). Per iteration: 8 front-batched streaming LDG.128 (two output
// patches), 2 coalesced STG.128. Mask write fused. Traffic 189 MB,
// DRAM-bound at ~7 TB/s combined (~87% of spec) — at the floor.

static constexpr int B_ = 8;
static constexpr int GRID_ = 64;
static constexpr int S_ = GRID_ * GRID_;     // 4096
static constexpr int H_ = 1152;
static constexpr int C4_ = H_ / 4;           // 288 float4 per row
static constexpr int OG_ = 32;               // output grid 32x32
static constexpr int L_ = OG_ * OG_;         // 1024
static constexpr int OUT_ELEMS_ = B_ * L_ * H_;  // 9437184
static constexpr int MASK_ELEMS_ = B_ * L_;      // 8192

static constexpr int THREADS_ = 256;
static constexpr int BLOCKS_ = 148 * 8;          // one full resident wave
static constexpr int STRIDE_ = THREADS_ * BLOCKS_;  // 303104

// sqrt(1152)/4
static constexpr float SCALE_ = 8.485281374238570f;

__global__ __launch_bounds__(THREADS_, 8)
void pool2x2_persist_kernel(const float4* __restrict__ in,
                            float4* __restrict__ out,
                            float* __restrict__ mask_tail,
                            int write_mask) {
    constexpr int total_pairs = B_ * (L_ / 2) * C4_;   // 1,179,648
    int tid0 = blockIdx.x * THREADS_ + threadIdx.x;

    // fused mask write: first MASK_ELEMS_ threads each write one 1.0f
    if (write_mask && tid0 < MASK_ELEMS_) {
        mask_tail[tid0] = 1.0f;
    }

    #pragma unroll 1
    for (int idx = tid0; idx < total_pairs; idx += STRIDE_) {
        int c = idx % C4_;
        int r = idx / C4_;          // r in [0, B*512)
        int op = r % (L_ / 2);      // output-pair index in [0,512)
        int b  = r / (L_ / 2);

        int o0 = op * 2;            // even output index; o1 = o0+1 shares oy
        int ox = o0 & (OG_ - 1);    // even, in [0,30]
        int oy = o0 >> 5;

        // top-left source patch of output o0; o1 pools s0+2..3 (+64 row)
        int s0 = (oy * 2) * GRID_ + ox * 2;

        const float4* base = in + ((size_t)b * S_ + s0) * C4_ + c;

        // 8 independent streaming loads, front-batched
        float4 r0 = __ldcs(base + 0 * C4_);
        float4 r1 = __ldcs(base + 1 * C4_);
        float4 r2 = __ldcs(base + 2 * C4_);
        float4 r3 = __ldcs(base + 3 * C4_);
        float4 r4 = __ldcs(base + (size_t)(GRID_ + 0) * C4_);
        float4 r5 = __ldcs(base + (size_t)(GRID_ + 1) * C4_);
        float4 r6 = __ldcs(base + (size_t)(GRID_ + 2) * C4_);
        float4 r7 = __ldcs(base + (size_t)(GRID_ + 3) * C4_);

        float4 w0, w1;
        w0.x = ((r0.x + r1.x) + (r4.x + r5.x)) * SCALE_;
        w0.y = ((r0.y + r1.y) + (r4.y + r5.y)) * SCALE_;
        w0.z = ((r0.z + r1.z) + (r4.z + r5.z)) * SCALE_;
        w0.w = ((r0.w + r1.w) + (r4.w + r5.w)) * SCALE_;
        w1.x = ((r2.x + r3.x) + (r6.x + r7.x)) * SCALE_;
        w1.y = ((r2.y + r3.y) + (r6.y + r7.y)) * SCALE_;
        w1.z = ((r2.z + r3.z) + (r6.z + r7.z)) * SCALE_;
        w1.w = ((r2.w + r3.w) + (r6.w + r7.w)) * SCALE_;

        float4* outp = out + ((size_t)b * L_ + o0) * C4_ + c;
        __stcs(outp, w0);
        __stcs(outp + C4_, w1);
    }
}

extern "C" void kernel_launch(void* const* d_in, const int* in_sizes, int n_in,
                              void* d_out, int out_size) {
    const float4* in = (const float4*)d_in[0];
    float4* out = (float4*)d_out;

    int write_mask = (out_size > OUT_ELEMS_) ? 1 : 0;
    float* mask_tail = (float*)d_out + OUT_ELEMS_;

    pool2x2_persist_kernel<<<BLOCKS_, THREADS_>>>(in, out, mask_tail, write_mask);
}